// round 16
// baseline (speedup 1.0000x reference)
#include <cuda_runtime.h>
#include <cstdint>

#define DIM        2048
#define NEXP       8
#define TILE_T     64          // tokens per tile (2 per consumer lane)
#define NSTRIPS    4           // strips per block, 1 consumer + 1 producer warp each
#define THREADS    256         // warps 0-3 consumers, 4-7 producers
#define HALF_COLS  1024
#define COLS_PER_STRIP 256
#define STAGE_COLS 16
#define NSTAGES    (COLS_PER_STRIP / STAGE_COLS)  // 16
#define NBUF       3
#define CHUNKS     (STAGE_COLS / 4)               // 4
#define STAGE_BYTES (TILE_T * STAGE_COLS * 4)     // 4096
#define STRIP_SMEM (NBUF * STAGE_BYTES)           // 12288
#define SMEM_TOTAL (NSTRIPS * STRIP_SMEM)         // 49152
#define MOE_COEFF  0.01f
#define MAX_TILES  256

__device__ float        g_part[MAX_TILES * 2 * TILE_T * NEXP];
__device__ float        g_imp_part[MAX_TILES * NEXP];
__device__ float        g_load_part[MAX_TILES * NEXP];
__device__ unsigned int g_tile_tick[MAX_TILES];
__device__ unsigned int g_ticket = 0;

__device__ __forceinline__ void strip_bar(int id) {
    asm volatile("bar.sync %0, 64;" :: "r"(id) : "memory");
}

__global__ void __launch_bounds__(THREADS, 3)
gate_kernel(const float* __restrict__ x, const float* __restrict__ W,
            float* __restrict__ out, int half, int ntok, int auxPos, int ntiles) {
    extern __shared__ char smem[];
    float* logitsBuf = reinterpret_cast<float*>(smem);   // union over staging

    const int tid  = threadIdx.x;
    const int w    = tid >> 5;
    const int lane = tid & 31;
    const int tile = blockIdx.x >> 1;
    const int hIdx = blockIdx.x & 1;
    const int tok0 = tile * TILE_T;

    if (w >= NSTRIPS) {
        // ================= PRODUCER warp (strip = w-4) =================
        const int strip = w - NSTRIPS;
        const int colBase = hIdx * HALF_COLS + strip * COLS_PER_STRIP;
        const unsigned int stripBase = (unsigned int)__cvta_generic_to_shared(
            smem + strip * STRIP_SMEM);
        const int c_st  = lane & 3;      // float4 chunk within 64 B row
        const int r0_st = lane >> 2;     // base row 0..7

        #define ISSUE_STAGE(t)                                                  \
        {                                                                       \
            const unsigned int base_ = stripBase + ((t) % NBUF) * STAGE_BYTES;  \
            const float* src0_ = x + (size_t)(tok0 + r0_st) * DIM               \
                                   + colBase + (t) * STAGE_COLS + c_st * 4;     \
            _Pragma("unroll")                                                   \
            for (int j = 0; j < 8; j++) {                                       \
                const int r_ = r0_st + j * 8;                                   \
                const unsigned int dst_ =                                       \
                    base_ + r_ * 64 + ((c_st ^ ((r_ >> 1) & 3)) * 16);          \
                asm volatile("cp.async.cg.shared.global [%0], [%1], 16;"        \
                             :: "r"(dst_), "l"(src0_ + (size_t)j * 8 * DIM));   \
            }                                                                   \
            asm volatile("cp.async.commit_group;");                             \
        }

        ISSUE_STAGE(0); ISSUE_STAGE(1);
        #pragma unroll 1
        for (int s = 0; s < NSTAGES; s++) {
            asm volatile("cp.async.wait_group 1;");  // stage s landed in smem
            strip_bar(strip + 1);                    // publish s; buffer (s+2)%3 free
            if (s + 2 < NSTAGES) {
                ISSUE_STAGE(s + 2);
            } else {
                asm volatile("cp.async.commit_group;");  // keep count uniform
            }
        }
        asm volatile("cp.async.wait_group 0;");
        __syncthreads();          // join consumers at epilogue
        __syncthreads();          // matches consumers' second sync
        return;                   // producers exit; epilogue below is w==0 only
    }

    // ================= CONSUMER warp (strip = w) =================
    const int strip = w;
    const int colBase = hIdx * HALF_COLS + strip * COLS_PER_STRIP;
    const char* stripBuf = smem + strip * STRIP_SMEM;

    float accA[NEXP], accB[NEXP];
    #pragma unroll
    for (int e = 0; e < NEXP; e++) { accA[e] = 0.0f; accB[e] = 0.0f; }

    const float4* W4 = reinterpret_cast<const float4*>(W);
    const int swz = (lane >> 1) & 3;   // rows lane and lane+32 share swizzle
    const char* rowAp = stripBuf + lane * 64;
    const char* rowBp = stripBuf + (lane + 32) * 64;

    #pragma unroll 1
    for (int s = 0; s < NSTAGES; s++) {
        strip_bar(strip + 1);                        // stage s ready
        const int bo = (s % NBUF) * STAGE_BYTES;
        const int wcol = (colBase >> 2) + s * CHUNKS;
        #pragma unroll
        for (int c = 0; c < CHUNKS; c++) {
            const int co = bo + ((c ^ swz) * 16);
            float4 xa = *reinterpret_cast<const float4*>(rowAp + co);
            float4 xb = *reinterpret_cast<const float4*>(rowBp + co);
            #pragma unroll
            for (int e = 0; e < NEXP; e++) {
                float4 wv = __ldg(&W4[e * (DIM / 4) + wcol + c]);
                accA[e] = fmaf(xa.x, wv.x,
                          fmaf(xa.y, wv.y,
                          fmaf(xa.z, wv.z,
                          fmaf(xa.w, wv.w, accA[e]))));
                accB[e] = fmaf(xb.x, wv.x,
                          fmaf(xb.y, wv.y,
                          fmaf(xb.z, wv.z,
                          fmaf(xb.w, wv.w, accB[e]))));
            }
        }
    }
    __syncthreads();    // all strips done; staging smem now dead

    // per-lane partial logits -> smem (row stride 9 words: conflict-free)
    {
        float* lrowA = logitsBuf + (w * TILE_T + lane) * 9;
        float* lrowB = logitsBuf + (w * TILE_T + lane + 32) * 9;
        #pragma unroll
        for (int e = 0; e < NEXP; e++) {
            lrowA[e] = accA[e];
            lrowB[e] = accB[e];
        }
    }
    __syncthreads();

    if (w == 0) {
        // reduce 4 strip partials, write this half's 64x8 partial to scratch
        float4* myPart = reinterpret_cast<float4*>(
            g_part + ((size_t)(tile * 2 + hIdx) * TILE_T) * NEXP);
        #pragma unroll
        for (int half_t = 0; half_t < 2; half_t++) {
            const int tloc = lane + half_t * 32;
            float lg[NEXP];
            #pragma unroll
            for (int e = 0; e < NEXP; e++) {
                float sum = 0.0f;
                #pragma unroll
                for (int ww = 0; ww < NSTRIPS; ww++)
                    sum += logitsBuf[(ww * TILE_T + tloc) * 9 + e];
                lg[e] = sum;
            }
            myPart[tloc * 2 + 0] = make_float4(lg[0], lg[1], lg[2], lg[3]);
            myPart[tloc * 2 + 1] = make_float4(lg[4], lg[5], lg[6], lg[7]);
        }
        __threadfence();

        unsigned old = 0;
        if (lane == 0) old = atomicAdd(&g_tile_tick[tile], 1u);
        old = __shfl_sync(0xffffffffu, old, 0);
        if (old != 1u) return;          // first arriver: done
        __threadfence();

        // ---- finisher: combine halves (fixed order -> deterministic) ----
        const float4* p0 = reinterpret_cast<const float4*>(
            g_part + ((size_t)(tile * 2 + 0) * TILE_T) * NEXP);
        const float4* p1 = reinterpret_cast<const float4*>(
            g_part + ((size_t)(tile * 2 + 1) * TILE_T) * NEXP);

        float impLoc[NEXP];
        #pragma unroll
        for (int e = 0; e < NEXP; e++) impLoc[e] = 0.0f;
        int top1[2];

        #pragma unroll
        for (int half_t = 0; half_t < 2; half_t++) {
            const int tloc = lane + half_t * 32;
            float4 a0 = p0[tloc * 2 + 0], a1 = p0[tloc * 2 + 1];
            float4 b0 = p1[tloc * 2 + 0], b1 = p1[tloc * 2 + 1];
            float lg[NEXP] = {a0.x + b0.x, a0.y + b0.y, a0.z + b0.z, a0.w + b0.w,
                              a1.x + b1.x, a1.y + b1.y, a1.z + b1.z, a1.w + b1.w};
            float m = lg[0];
            #pragma unroll
            for (int e = 1; e < NEXP; e++) m = fmaxf(m, lg[e]);
            float p[NEXP], psum = 0.0f;
            #pragma unroll
            for (int e = 0; e < NEXP; e++) { p[e] = __expf(lg[e] - m); psum += p[e]; }
            float inv = 1.0f / psum;
            #pragma unroll
            for (int e = 0; e < NEXP; e++) { p[e] *= inv; impLoc[e] += p[e]; }

            // top-1 / top-2 (first max wins: matches jax tie rule)
            int e0 = 0; float v0 = p[0];
            #pragma unroll
            for (int e = 1; e < NEXP; e++) if (p[e] > v0) { v0 = p[e]; e0 = e; }
            int e1 = (e0 == 0) ? 1 : 0; float v1 = p[e1];
            #pragma unroll
            for (int e = 0; e < NEXP; e++)
                if (e != e0 && p[e] > v1) { v1 = p[e]; e1 = e; }
            top1[half_t] = e0;

            float rs = 1.0f / (v0 + v1);
            const int tok = tok0 + tloc;
            out[tok * 2 + 0] = v0 * rs;
            out[tok * 2 + 1] = v1 * rs;
            out[half + tok * 2 + 0] = (float)e0;
            out[half + tok * 2 + 1] = (float)e1;
        }

        // per-tile aux statistics
        #pragma unroll
        for (int e = 0; e < NEXP; e++) {
            float v = impLoc[e];
            #pragma unroll
            for (int o = 16; o; o >>= 1) v += __shfl_xor_sync(0xffffffffu, v, o);
            unsigned bal0 = __ballot_sync(0xffffffffu, top1[0] == e);
            unsigned bal1 = __ballot_sync(0xffffffffu, top1[1] == e);
            if (lane == 0) {
                g_imp_part[tile * NEXP + e]  = v;
                g_load_part[tile * NEXP + e] = (float)(__popc(bal0) + __popc(bal1));
            }
        }
        if (lane == 0) g_tile_tick[tile] = 0;   // reset for next graph replay
        __threadfence();

        // last-tile finalize (global ticket; self-resetting)
        unsigned old2 = 0;
        if (lane == 0) old2 = atomicAdd(&g_ticket, 1u);
        old2 = __shfl_sync(0xffffffffu, old2, 0);
        if (old2 == (unsigned)(ntiles - 1)) {
            __threadfence();
            const int e = lane & 7;
            const int q = lane >> 3;
            const int per = ntiles / 4;
            float si = 0.0f, sl = 0.0f;
            for (int b = q * per; b < (q + 1) * per; b++) {
                si += __ldcg(&g_imp_part[b * NEXP + e]);
                sl += __ldcg(&g_load_part[b * NEXP + e]);
            }
            si += __shfl_xor_sync(0xffffffffu, si, 8);
            si += __shfl_xor_sync(0xffffffffu, si, 16);
            sl += __shfl_xor_sync(0xffffffffu, sl, 8);
            sl += __shfl_xor_sync(0xffffffffu, sl, 16);
            float invN = 1.0f / (float)ntok;
            float prod = (si * invN) * (sl * invN);
            prod += __shfl_xor_sync(0xffffffffu, prod, 1);
            prod += __shfl_xor_sync(0xffffffffu, prod, 2);
            prod += __shfl_xor_sync(0xffffffffu, prod, 4);
            if (lane == 0) {
                out[auxPos] = (float)NEXP * prod * MOE_COEFF;
                g_ticket = 0;
            }
        }
    }
}

extern "C" void kernel_launch(void* const* d_in, const int* in_sizes, int n_in,
                              void* d_out, int out_size) {
    const float* x = (const float*)d_in[0];
    const float* W = (const float*)d_in[1];
    float* out = (float*)d_out;

    const int ntok   = in_sizes[0] / DIM;        // 16384
    const int half   = (out_size - 1) / 2;       // 32768
    const int ntiles = ntok / TILE_T;            // 256
    const int grid   = ntiles * 2;               // 512

    static bool attrDone = false;
    if (!attrDone) {
        cudaFuncSetAttribute(gate_kernel,
                             cudaFuncAttributeMaxDynamicSharedMemorySize, SMEM_TOTAL);
        attrDone = true;
    }

    gate_kernel<<<grid, THREADS, SMEM_TOTAL>>>(x, W, out, half, ntok,
                                               out_size - 1, ntiles);
}

// round 17
// speedup vs baseline: 1.3952x; 1.3952x over previous
#include <cuda_runtime.h>
#include <cstdint>

#define DIM        2048
#define NEXP       8
#define TILE_T     64          // tokens per block (2 per lane)
#define WARPS      8
#define THREADS    (WARPS * 32)
#define STAGE_COLS 16          // per warp per stage; block covers 128 cols/stage
#define NSTAGES    16
#define NBUF       3
#define CHUNKS     (STAGE_COLS / 4)   // 4 float4 per row per stage
#define STAGE_BYTES (TILE_T * STAGE_COLS * 4)    // 4096
#define WARP_SMEM  (NBUF * STAGE_BYTES)          // 12288
#define SMEM_TOTAL (WARPS * WARP_SMEM)           // 98304
#define MOE_COEFF  0.01f
#define MAX_BLOCKS 1024

__device__ float        g_imp_part[MAX_BLOCKS * NEXP];
__device__ float        g_load_part[MAX_BLOCKS * NEXP];
__device__ unsigned int g_ticket = 0;

__device__ __forceinline__ unsigned long long ffma2(unsigned long long a,
                                                    unsigned long long b,
                                                    unsigned long long c) {
    unsigned long long d;
    asm("fma.rn.f32x2 %0, %1, %2, %3;" : "=l"(d) : "l"(a), "l"(b), "l"(c));
    return d;
}
__device__ __forceinline__ float2 unpack2(unsigned long long d) {
    float2 r;
    asm("mov.b64 {%0, %1}, %2;" : "=f"(r.x), "=f"(r.y) : "l"(d));
    return r;
}

__global__ void __launch_bounds__(THREADS, 2)
gate_kernel(const float* __restrict__ x, const float* __restrict__ W,
            float* __restrict__ out, int half, int ntok, int auxPos) {
    extern __shared__ char smem[];
    float* logitsBuf = reinterpret_cast<float*>(smem);   // union over staging

    const int tid  = threadIdx.x;
    const int w    = tid >> 5;
    const int lane = tid & 31;
    const int tok0 = blockIdx.x * TILE_T;
    // INTERLEAVED strips: warp w, stage s covers cols [s*128 + w*16, +16).
    // Block-wide each stage reads a contiguous 512 B run of every token row;
    // stages sweep the 8 KB row sequentially -> DRAM row locality.
    const int colOff = w * STAGE_COLS;          // within the 128-col stage block

    char* warpBuf = smem + w * WARP_SMEM;
    const unsigned int warpBase =
        (unsigned int)__cvta_generic_to_shared(warpBuf);

    const int c_st  = lane & 3;      // float4 chunk within 64 B row
    const int r0_st = lane >> 2;     // base row 0..7

    // ---- stage t: 64 rows x 16 cols (R2/R12-proven fill + swizzle) ----
    #define ISSUE_STAGE(t)                                                      \
    {                                                                           \
        const int bi_ = (t) % NBUF;                                             \
        const unsigned int base_ = warpBase + bi_ * STAGE_BYTES;                \
        const float* src0_ = x + (size_t)(tok0 + r0_st) * DIM                   \
                               + (t) * 128 + colOff + c_st * 4;                 \
        _Pragma("unroll")                                                       \
        for (int j = 0; j < 8; j++) {                                           \
            const int r_ = r0_st + j * 8;                                       \
            const unsigned int dst_ =                                           \
                base_ + r_ * 64 + ((c_st ^ ((r_ >> 1) & 3)) * 16);              \
            asm volatile("cp.async.cg.shared.global [%0], [%1], 16;"            \
                         :: "r"(dst_), "l"(src0_ + (size_t)j * 8 * DIM));       \
        }                                                                       \
        asm volatile("cp.async.commit_group;");                                 \
    }

    unsigned long long accA[NEXP], accB[NEXP];
    #pragma unroll
    for (int e = 0; e < NEXP; e++) { accA[e] = 0ULL; accB[e] = 0ULL; }

    ISSUE_STAGE(0); ISSUE_STAGE(1); ISSUE_STAGE(2);

    const ulonglong2* W2 = reinterpret_cast<const ulonglong2*>(W);
    const int swz = (lane >> 1) & 3;   // rows lane and lane+32 share swizzle
    const char* rowAp = warpBuf + lane * 64;
    const char* rowBp = warpBuf + (lane + 32) * 64;

    #pragma unroll 1
    for (int s = 0; s < NSTAGES; s++) {
        asm volatile("cp.async.wait_group 2;");   // group s complete (2 ahead)
        __syncwarp();
        const int bo = (s % NBUF) * STAGE_BYTES;
        // W cols match the interleaved x strip: float4 index = s*32 + w*4
        const int wcol = s * 32 + w * 4;
        #pragma unroll
        for (int c = 0; c < CHUNKS; c++) {
            const int co = bo + ((c ^ swz) * 16);
            ulonglong2 xa = *reinterpret_cast<const ulonglong2*>(rowAp + co);
            ulonglong2 xb = *reinterpret_cast<const ulonglong2*>(rowBp + co);
            #pragma unroll
            for (int e = 0; e < NEXP; e++) {
                ulonglong2 wv = __ldg(&W2[e * (DIM / 4) + wcol + c]);
                accA[e] = ffma2(xa.x, wv.x, accA[e]);
                accA[e] = ffma2(xa.y, wv.y, accA[e]);
                accB[e] = ffma2(xb.x, wv.x, accB[e]);
                accB[e] = ffma2(xb.y, wv.y, accB[e]);
            }
        }
        __syncwarp();
        if (s + NBUF < NSTAGES) {
            ISSUE_STAGE(s + NBUF);          // refills the buffer just consumed
        } else {
            asm volatile("cp.async.commit_group;");   // keep group count exact
        }
    }

    asm volatile("cp.async.wait_group 0;");
    __syncthreads();

    // per-lane partial logits -> smem (row stride 9 words: conflict-free)
    {
        float* lrowA = logitsBuf + (w * TILE_T + lane) * 9;
        float* lrowB = logitsBuf + (w * TILE_T + lane + 32) * 9;
        #pragma unroll
        for (int e = 0; e < NEXP; e++) {
            float2 tA = unpack2(accA[e]);
            float2 tB = unpack2(accB[e]);
            lrowA[e] = tA.x + tA.y;
            lrowB[e] = tB.x + tB.y;
        }
    }
    __syncthreads();

    if (w == 0) {
        float impLoc[NEXP];
        #pragma unroll
        for (int e = 0; e < NEXP; e++) impLoc[e] = 0.0f;
        int top1[2];

        #pragma unroll
        for (int half_t = 0; half_t < 2; half_t++) {
            const int tloc = lane + half_t * 32;
            float lg[NEXP];
            #pragma unroll
            for (int e = 0; e < NEXP; e++) {
                float sum = 0.0f;
                #pragma unroll
                for (int ww = 0; ww < WARPS; ww++)
                    sum += logitsBuf[(ww * TILE_T + tloc) * 9 + e];
                lg[e] = sum;
            }
            float m = lg[0];
            #pragma unroll
            for (int e = 1; e < NEXP; e++) m = fmaxf(m, lg[e]);
            float p[NEXP], psum = 0.0f;
            #pragma unroll
            for (int e = 0; e < NEXP; e++) { p[e] = __expf(lg[e] - m); psum += p[e]; }
            float inv = 1.0f / psum;
            #pragma unroll
            for (int e = 0; e < NEXP; e++) { p[e] *= inv; impLoc[e] += p[e]; }

            // top-1 / top-2 (first max wins: matches jax tie rule)
            int e0 = 0; float v0 = p[0];
            #pragma unroll
            for (int e = 1; e < NEXP; e++) if (p[e] > v0) { v0 = p[e]; e0 = e; }
            int e1 = (e0 == 0) ? 1 : 0; float v1 = p[e1];
            #pragma unroll
            for (int e = 0; e < NEXP; e++)
                if (e != e0 && p[e] > v1) { v1 = p[e]; e1 = e; }
            top1[half_t] = e0;

            float rs = 1.0f / (v0 + v1);
            const int tok = tok0 + tloc;
            out[tok * 2 + 0] = v0 * rs;
            out[tok * 2 + 1] = v1 * rs;
            out[half + tok * 2 + 0] = (float)e0;
            out[half + tok * 2 + 1] = (float)e1;
        }

        // per-block aux statistics -> scratch
        #pragma unroll
        for (int e = 0; e < NEXP; e++) {
            float v = impLoc[e];
            #pragma unroll
            for (int o = 16; o; o >>= 1) v += __shfl_xor_sync(0xffffffffu, v, o);
            unsigned bal0 = __ballot_sync(0xffffffffu, top1[0] == e);
            unsigned bal1 = __ballot_sync(0xffffffffu, top1[1] == e);
            if (lane == 0) {
                g_imp_part[blockIdx.x * NEXP + e]  = v;
                g_load_part[blockIdx.x * NEXP + e] = (float)(__popc(bal0) + __popc(bal1));
            }
        }
        __threadfence();

        // last-block finalize (ticket resets itself each graph replay)
        unsigned old = 0;
        if (lane == 0) old = atomicAdd(&g_ticket, 1u);
        old = __shfl_sync(0xffffffffu, old, 0);
        if (old == gridDim.x - 1) {
            __threadfence();
            const int e = lane & 7;
            const int q = lane >> 3;
            const int per = gridDim.x / 4;
            float si = 0.0f, sl = 0.0f;
            for (int b = q * per; b < (q + 1) * per; b++) {
                si += __ldcg(&g_imp_part[b * NEXP + e]);
                sl += __ldcg(&g_load_part[b * NEXP + e]);
            }
            si += __shfl_xor_sync(0xffffffffu, si, 8);
            si += __shfl_xor_sync(0xffffffffu, si, 16);
            sl += __shfl_xor_sync(0xffffffffu, sl, 8);
            sl += __shfl_xor_sync(0xffffffffu, sl, 16);
            float invN = 1.0f / (float)ntok;
            float prod = (si * invN) * (sl * invN);
            prod += __shfl_xor_sync(0xffffffffu, prod, 1);
            prod += __shfl_xor_sync(0xffffffffu, prod, 2);
            prod += __shfl_xor_sync(0xffffffffu, prod, 4);
            if (lane == 0) {
                out[auxPos] = (float)NEXP * prod * MOE_COEFF;
                g_ticket = 0;
            }
        }
    }
}

extern "C" void kernel_launch(void* const* d_in, const int* in_sizes, int n_in,
                              void* d_out, int out_size) {
    const float* x = (const float*)d_in[0];
    const float* W = (const float*)d_in[1];
    float* out = (float*)d_out;

    const int ntok = in_sizes[0] / DIM;          // 16384
    const int half = (out_size - 1) / 2;         // 32768
    const int grid = ntok / TILE_T;              // 256

    static bool attrDone = false;
    if (!attrDone) {
        cudaFuncSetAttribute(gate_kernel,
                             cudaFuncAttributeMaxDynamicSharedMemorySize, SMEM_TOTAL);
        attrDone = true;
    }

    gate_kernel<<<grid, THREADS, SMEM_TOTAL>>>(x, W, out, half, ntok,
                                               out_size - 1);
}